// round 2
// baseline (speedup 1.0000x reference)
#include <cuda_runtime.h>

// Problem constants (fixed by the reference):
//   B=8, S=4096, H=1024, SEG_PER_EX=64, NUM_SEG=512, P=4096
#define TOKS   32768      // B*S
#define HDIM   1024
#define NSEG   512
#define SEGEX  64
#define NPAIR  4096

// -------- device scratch (static allocation; no cudaMalloc allowed) --------
__device__ int   g_start[NSEG];
__device__ int   g_end[NSEG];
__device__ float g_means[NSEG * HDIM];        // 2 MB
__device__ float g_Hb[NSEG * 2 * HDIM];       // 4 MB: [s][0:H]=means@W1_top, [s][H:2H]=means@W1_bot

// ---------------------------------------------------------------------------
// packed f32x2 helpers (FFMA2 path — 2x fp32 FMA throughput vs scalar FFMA)
// ---------------------------------------------------------------------------
typedef unsigned long long u64;

__device__ __forceinline__ u64 pack2(float lo, float hi) {
    u64 r;
    asm("mov.b64 %0, {%1, %2};" : "=l"(r) : "f"(lo), "f"(hi));
    return r;
}
__device__ __forceinline__ void ffma2(u64& d, u64 a, u64 b) {
    asm("fma.rn.f32x2 %0, %1, %2, %0;" : "+l"(d) : "l"(a), "l"(b));
}
__device__ __forceinline__ void unpack2(u64 v, float& lo, float& hi) {
    asm("mov.b64 {%0, %1}, %2;" : "=f"(lo), "=f"(hi) : "l"(v));
}

// ---------------------------------------------------------------------------
// 0) init segment bounds (empty segments -> count 0 -> mean 0)
// ---------------------------------------------------------------------------
__global__ void init_kernel() {
    int i = blockIdx.x * blockDim.x + threadIdx.x;
    if (i < NSEG) { g_start[i] = 0; g_end[i] = 0; }
}

// ---------------------------------------------------------------------------
// 1) segment boundary detection. flat_seg = seg_ids[i] + (i/S)*SEGEX is
//    GLOBALLY sorted (rows sorted per example; example id ranges are disjoint
//    and increasing), so each segment is one contiguous token range.
// ---------------------------------------------------------------------------
__global__ void bounds_kernel(const int* __restrict__ seg) {
    int i = blockIdx.x * blockDim.x + threadIdx.x;
    if (i >= TOKS) return;
    int s  = seg[i] + (i >> 12) * SEGEX;                       // S = 4096 = 2^12
    int sp = (i > 0)        ? (seg[i - 1] + ((i - 1) >> 12) * SEGEX) : -1;
    int sn = (i < TOKS - 1) ? (seg[i + 1] + ((i + 1) >> 12) * SEGEX) : -1;
    if (s != sp) g_start[s] = i;
    if (s != sn) g_end[s]   = i + 1;
}

// ---------------------------------------------------------------------------
// 2) span mean pooling: block = (h-chunk of 256, segment). Coalesced 1KB
//    loads per chunk per token row; reads sequence_output exactly once (134MB).
// ---------------------------------------------------------------------------
__global__ __launch_bounds__(256) void pool_kernel(const float* __restrict__ tok) {
    int s = blockIdx.y;
    int h = (blockIdx.x << 8) + threadIdx.x;
    int st = g_start[s], en = g_end[s];
    const float* p = tok + (size_t)st * HDIM + h;
    float a0 = 0.f, a1 = 0.f, a2 = 0.f, a3 = 0.f;
    int i = st;
    for (; i + 4 <= en; i += 4, p += 4 * HDIM) {
        a0 += p[0];
        a1 += p[HDIM];
        a2 += p[2 * HDIM];
        a3 += p[3 * HDIM];
    }
    for (; i < en; ++i, p += HDIM) a0 += *p;
    float acc = (a0 + a1) + (a2 + a3);
    int cnt = en - st;
    g_means[s * HDIM + h] = acc / (float)(cnt > 0 ? cnt : 1);
}

// ---------------------------------------------------------------------------
// 3) GEMM: g_Hb[512, 2048] = g_means[512,1024] @ Wcat[1024, 2048]
//    where Wcat col n<1024  comes from W1 rows 0..1023    (H1 part)
//          Wcat col n>=1024 comes from W1 rows 1024..2047 (H2 part)
//    64x64 tiles, BK=16, 256 threads, 4x4 microtile, packed f32x2 FMAs.
//    A stored pre-duplicated as u64 pairs (no per-kk packing MOVs);
//    double-buffered smem, one __syncthreads per K-tile.
// ---------------------------------------------------------------------------
__global__ __launch_bounds__(256) void gemm_kernel(const float* __restrict__ W1) {
    __shared__ u64   As[2][16][66];   // [buf][k][m] duplicated (lo=hi=a), pad 2 for store banks
    __shared__ float Bs[2][16][64];   // [buf][k][n]

    int tid = threadIdx.x;
    int m0 = blockIdx.y << 6;
    int n0 = blockIdx.x << 6;
    // For n>=1024: W1[(1024+k)*1024 + (n-1024)] = (W1 + 1024*1024 - 1024)[k*1024 + n]
    const float* Bptr = W1 + ((n0 >= HDIM) ? ((size_t)HDIM * HDIM - HDIM) : 0);

    int tx = tid & 15, ty = tid >> 4;

    u64 acc[4][2];
    #pragma unroll
    for (int i = 0; i < 4; i++) { acc[i][0] = 0ull; acc[i][1] = 0ull; }

    int ar = tid >> 2, akq = (tid & 3) << 2;       // A tile: 64 rows x 16 k
    int bkr = tid >> 4, bnq = (tid & 15) << 2;     // B tile: 16 k-rows x 64 n
    const float* Aload = g_means + (size_t)(m0 + ar) * HDIM + akq;
    const float* Bload = Bptr + (size_t)bkr * HDIM + n0 + bnq;

    // preload tile 0
    {
        float4 a4 = *(const float4*)(Aload);
        float4 b4 = *(const float4*)(Bload);
        As[0][akq + 0][ar] = pack2(a4.x, a4.x);
        As[0][akq + 1][ar] = pack2(a4.y, a4.y);
        As[0][akq + 2][ar] = pack2(a4.z, a4.z);
        As[0][akq + 3][ar] = pack2(a4.w, a4.w);
        *(float4*)&Bs[0][bkr][bnq] = b4;
    }
    __syncthreads();

    const int T = HDIM / 16;   // 64 K-tiles
    for (int it = 0; it < T; ++it) {
        int cur = it & 1;
        float4 na, nb;
        if (it + 1 < T) {
            na = *(const float4*)(Aload + (it + 1) * 16);
            nb = *(const float4*)(Bload + (size_t)(it + 1) * 16 * HDIM);
        }
        #pragma unroll
        for (int kk = 0; kk < 16; ++kk) {
            ulonglong2 a01 = *(const ulonglong2*)&As[cur][kk][(ty << 2) + 0]; // a0,a1 (dup'd)
            ulonglong2 a23 = *(const ulonglong2*)&As[cur][kk][(ty << 2) + 2]; // a2,a3 (dup'd)
            ulonglong2 bq  = *(const ulonglong2*)&Bs[cur][kk][tx << 2];       // (b0,b1),(b2,b3)
            ffma2(acc[0][0], a01.x, bq.x); ffma2(acc[0][1], a01.x, bq.y);
            ffma2(acc[1][0], a01.y, bq.x); ffma2(acc[1][1], a01.y, bq.y);
            ffma2(acc[2][0], a23.x, bq.x); ffma2(acc[2][1], a23.x, bq.y);
            ffma2(acc[3][0], a23.y, bq.x); ffma2(acc[3][1], a23.y, bq.y);
        }
        if (it + 1 < T) {
            int nxt = cur ^ 1;
            As[nxt][akq + 0][ar] = pack2(na.x, na.x);
            As[nxt][akq + 1][ar] = pack2(na.y, na.y);
            As[nxt][akq + 2][ar] = pack2(na.z, na.z);
            As[nxt][akq + 3][ar] = pack2(na.w, na.w);
            *(float4*)&Bs[nxt][bkr][bnq] = nb;
            __syncthreads();
        }
    }

    #pragma unroll
    for (int i = 0; i < 4; i++) {
        float c0, c1, c2, c3;
        unpack2(acc[i][0], c0, c1);
        unpack2(acc[i][1], c2, c3);
        float* crow = g_Hb + (size_t)(m0 + (ty << 2) + i) * (2 * HDIM) + n0 + (tx << 2);
        crow[0] = c0; crow[1] = c1; crow[2] = c2; crow[3] = c3;
    }
}

// ---------------------------------------------------------------------------
// 4) per-pair epilogue: logit[p] = sum_j relu(H1[i0,j] + H2[i1,j] + b1[j]) * W2[j] + b2
//    One warp per pair; g_Hb (4MB) is L2-resident.
// ---------------------------------------------------------------------------
__global__ __launch_bounds__(256) void pair_kernel(const int* __restrict__ pair_idx,
                                                   const float* __restrict__ b1,
                                                   const float* __restrict__ W2,
                                                   const float* __restrict__ b2,
                                                   float* __restrict__ out) {
    int p = (blockIdx.x << 3) + (threadIdx.x >> 5);
    int lane = threadIdx.x & 31;
    int i0 = pair_idx[2 * p];
    int i1 = pair_idx[2 * p + 1];
    const float4* h0 = (const float4*)(g_Hb + (size_t)i0 * (2 * HDIM));
    const float4* h1 = (const float4*)(g_Hb + (size_t)i1 * (2 * HDIM) + HDIM);
    const float4* B1 = (const float4*)b1;
    const float4* w2 = (const float4*)W2;
    float acc = 0.f;
    #pragma unroll
    for (int j = lane; j < HDIM / 4; j += 32) {
        float4 x0 = h0[j], x1 = h1[j], bb = B1[j], ww = w2[j];
        acc = fmaf(fmaxf(x0.x + x1.x + bb.x, 0.f), ww.x, acc);
        acc = fmaf(fmaxf(x0.y + x1.y + bb.y, 0.f), ww.y, acc);
        acc = fmaf(fmaxf(x0.z + x1.z + bb.z, 0.f), ww.z, acc);
        acc = fmaf(fmaxf(x0.w + x1.w + bb.w, 0.f), ww.w, acc);
    }
    #pragma unroll
    for (int o = 16; o; o >>= 1) acc += __shfl_xor_sync(0xffffffffu, acc, o);
    if (lane == 0) out[p] = acc + b2[0];
}

// ---------------------------------------------------------------------------
extern "C" void kernel_launch(void* const* d_in, const int* in_sizes, int n_in,
                              void* d_out, int out_size) {
    const float* seq  = (const float*)d_in[0];  // [8,4096,1024] f32
    const int*   seg  = (const int*)d_in[1];    // [8,4096] i32
    const int*   pidx = (const int*)d_in[2];    // [4096,2] i32
    const float* W1   = (const float*)d_in[3];  // [2048,1024] f32
    const float* b1   = (const float*)d_in[4];  // [1024] f32
    const float* W2   = (const float*)d_in[5];  // [1024,1] f32
    const float* b2   = (const float*)d_in[6];  // [1] f32
    float* out = (float*)d_out;                 // [4096,1] f32

    init_kernel<<<2, 256>>>();
    bounds_kernel<<<TOKS / 256, 256>>>(seg);
    pool_kernel<<<dim3(HDIM / 256, NSEG), 256>>>(seq);
    gemm_kernel<<<dim3(2 * HDIM / 64, NSEG / 64), 256>>>(W1);
    pair_kernel<<<NPAIR / 8, 256>>>(pidx, b1, W2, b2, out);
}

// round 4
// speedup vs baseline: 1.6743x; 1.6743x over previous
#include <cuda_runtime.h>
#include <cuda_bf16.h>
#include <cstdint>

// Problem constants: B=8, S=4096, H=1024, SEG_PER_EX=64, NUM_SEG=512, P=4096
#define TOKS   32768
#define HDIM   1024
#define NSEG   512
#define SEGEX  64
#define NPAIR  4096
#define KCAT   3072             // 3*HDIM concatenated split-K (hi|lo|hi vs hi|hi|lo)
#define CHUNK  64               // K elements per pipeline stage
#define NCHUNK (KCAT / CHUNK)   // 48
#define NSTAGE 3
#define STAGE_BYTES 24576       // A 64x64 bf16 (8KB) + B 128x64 bf16 (16KB)
#define SMEM_TOTAL (NSTAGE * STAGE_BYTES)   // 73728

// -------- device scratch (static; no cudaMalloc allowed) --------
__device__ __align__(128) __nv_bfloat16 g_Acat[NSEG * KCAT];       // 3 MB  [m][ Ahi | Alo | Ahi ]
__device__ __align__(128) __nv_bfloat16 g_Bcat[2 * HDIM * KCAT];   // 12 MB [n][ Bhi | Bhi | Blo ]
__device__ float g_Hb[NSEG * 2 * HDIM];                            // 4 MB  [s][0:H]=H1, [s][H:2H]=H2
__device__ int   g_start[NSEG];
__device__ int   g_end[NSEG];

__device__ __forceinline__ uint32_t smem_u32(const void* p) {
    uint32_t a;
    asm("{ .reg .u64 t; cvta.to.shared.u64 t, %1; cvt.u32.u64 %0, t; }" : "=r"(a) : "l"(p));
    return a;
}
#define CP_ASYNC16(dst, src) \
    asm volatile("cp.async.cg.shared.global [%0], [%1], 16;" :: "r"(dst), "l"(src))
#define CP_COMMIT() asm volatile("cp.async.commit_group;")
#define CP_WAIT(N)  asm volatile("cp.async.wait_group %0;" :: "n"(N))

#define LDMATRIX_X4(r0, r1, r2, r3, addr) \
    asm volatile("ldmatrix.sync.aligned.m8n8.x4.shared.b16 {%0,%1,%2,%3}, [%4];" \
        : "=r"(r0), "=r"(r1), "=r"(r2), "=r"(r3) : "r"(addr))

#define MMA_BF16(c0, c1, c2, c3, a0, a1, a2, a3, b0, b1) \
    asm volatile("mma.sync.aligned.m16n8k16.row.col.f32.bf16.bf16.f32 " \
        "{%0,%1,%2,%3}, {%4,%5,%6,%7}, {%8,%9}, {%0,%1,%2,%3};" \
        : "+f"(c0), "+f"(c1), "+f"(c2), "+f"(c3) \
        : "r"(a0), "r"(a1), "r"(a2), "r"(a3), "r"(b0), "r"(b1))

// smem tile addressing: rows of 64 bf16 = 128 B; 16B-unit column swizzled by row
__device__ __forceinline__ uint32_t sw_off(int row, int c16) {
    return (uint32_t)(row * 128 + ((c16 ^ (row & 7)) << 4));
}

// ---------------------------------------------------------------------------
// 0) init segment bounds
// ---------------------------------------------------------------------------
__global__ void init_kernel() {
    int i = blockIdx.x * blockDim.x + threadIdx.x;
    if (i < NSEG) { g_start[i] = 0; g_end[i] = 0; }
}

// ---------------------------------------------------------------------------
// 1) segment boundaries (flat_seg globally sorted -> contiguous token ranges)
// ---------------------------------------------------------------------------
__global__ void bounds_kernel(const int* __restrict__ seg) {
    int i = blockIdx.x * blockDim.x + threadIdx.x;
    if (i >= TOKS) return;
    int s  = seg[i] + (i >> 12) * SEGEX;
    int sp = (i > 0)        ? (seg[i - 1] + ((i - 1) >> 12) * SEGEX) : -1;
    int sn = (i < TOKS - 1) ? (seg[i + 1] + ((i + 1) >> 12) * SEGEX) : -1;
    if (s != sp) g_start[s] = i;
    if (s != sn) g_end[s]   = i + 1;
}

// ---------------------------------------------------------------------------
// 2) span mean pooling fused with bf16 hi/lo split: A_cat = [hi | lo | hi]
// ---------------------------------------------------------------------------
__global__ __launch_bounds__(256) void pool_kernel(const float* __restrict__ tok) {
    int s = blockIdx.y;
    int h = (blockIdx.x << 8) + threadIdx.x;
    int st = g_start[s], en = g_end[s];
    const float* p = tok + (size_t)st * HDIM + h;
    float a0 = 0.f, a1 = 0.f, a2 = 0.f, a3 = 0.f;
    int i = st;
    for (; i + 4 <= en; i += 4, p += 4 * HDIM) {
        a0 += p[0]; a1 += p[HDIM]; a2 += p[2 * HDIM]; a3 += p[3 * HDIM];
    }
    for (; i < en; ++i, p += HDIM) a0 += *p;
    int cnt = en - st;
    float mean = ((a0 + a1) + (a2 + a3)) / (float)(cnt > 0 ? cnt : 1);
    __nv_bfloat16 hi = __float2bfloat16(mean);
    __nv_bfloat16 lo = __float2bfloat16(mean - __bfloat162float(hi));
    size_t base = (size_t)s * KCAT;
    g_Acat[base + h]            = hi;
    g_Acat[base + HDIM + h]     = lo;
    g_Acat[base + 2 * HDIM + h] = hi;
}

// ---------------------------------------------------------------------------
// 2b) B_cat[n][k] = Wcat[k][n] split into [hi | hi | lo], via smem transpose.
//     Wcat[k,n] = n<H ? W1[k*H + n] : W1[(H+k)*H + (n-H)]
// ---------------------------------------------------------------------------
__global__ __launch_bounds__(256) void convB_kernel(const float* __restrict__ W1) {
    __shared__ float s[64][65];
    int n0 = blockIdx.x << 6;
    int k0 = blockIdx.y << 6;
    int t = threadIdx.x;
    const float* Wb = W1 + ((n0 >= HDIM) ? ((size_t)HDIM * HDIM - HDIM) : 0);
    {
        int kl = t >> 2, nq = (t & 3) << 4;
        const float4* src = (const float4*)(Wb + (size_t)(k0 + kl) * HDIM + n0 + nq);
        #pragma unroll
        for (int j = 0; j < 4; ++j) {
            float4 v = src[j];
            s[kl][nq + 4 * j + 0] = v.x;
            s[kl][nq + 4 * j + 1] = v.y;
            s[kl][nq + 4 * j + 2] = v.z;
            s[kl][nq + 4 * j + 3] = v.w;
        }
    }
    __syncthreads();
    {
        int nl = t >> 2, kq = (t & 3) << 4;
        __nv_bfloat16 hi[16], lo[16];
        #pragma unroll
        for (int j = 0; j < 16; ++j) {
            float v = s[kq + j][nl];
            hi[j] = __float2bfloat16(v);
            lo[j] = __float2bfloat16(v - __bfloat162float(hi[j]));
        }
        size_t base = (size_t)(n0 + nl) * KCAT + k0 + kq;
        uint4* dhi0 = (uint4*)(g_Bcat + base);
        uint4* dhi1 = (uint4*)(g_Bcat + base + HDIM);
        uint4* dlo  = (uint4*)(g_Bcat + base + 2 * HDIM);
        uint4 h0 = ((const uint4*)hi)[0], h1 = ((const uint4*)hi)[1];
        uint4 l0 = ((const uint4*)lo)[0], l1 = ((const uint4*)lo)[1];
        dhi0[0] = h0; dhi0[1] = h1;
        dhi1[0] = h0; dhi1[1] = h1;
        dlo[0]  = l0; dlo[1]  = l1;
    }
}

// ---------------------------------------------------------------------------
// 3) mma.sync GEMM: g_Hb[512,2048] = A_cat[512,3072] @ B_cat[2048,3072]^T
//    CTA tile 64(m) x 128(n), 8 warps (2x4), warp tile 32x32, K chunks of 64,
//    3-stage cp.async pipeline, ldmatrix fragment loads, m16n8k16 bf16 mma.
// ---------------------------------------------------------------------------
__global__ __launch_bounds__(256) void mma_gemm_kernel() {
    extern __shared__ __align__(128) char smem[];
    const uint32_t sb = smem_u32(smem);
    const int tid  = threadIdx.x;
    const int wid  = tid >> 5, lane = tid & 31;
    const int wm   = wid >> 2;         // 0..1  (m warp), rows wm*32
    const int wn   = wid & 3;          // 0..3  (n warp), cols wn*32
    const int m0   = blockIdx.y << 6;  // 512 / 64  = 8
    const int n0   = blockIdx.x << 7;  // 2048 / 128 = 16

    // ---- cp.async load mapping (per thread, per stage): 2 A units + 4 B units of 16B
    const int ra0 = tid >> 3,          ca0 = tid & 7;          // A row 0..31
    const int ra1 = (tid + 256) >> 3,  ca1 = tid & 7;          // A row 32..63
    const char* gA0 = (const char*)(g_Acat + (size_t)(m0 + ra0) * KCAT + ca0 * 8);
    const char* gA1 = (const char*)(g_Acat + (size_t)(m0 + ra1) * KCAT + ca1 * 8);
    const uint32_t oA0 = sw_off(ra0, ca0), oA1 = sw_off(ra1, ca1);
    const char* gB[4];
    uint32_t oB[4];
    #pragma unroll
    for (int j = 0; j < 4; ++j) {
        int u = tid + 256 * j;
        int nr = u >> 3, c16 = u & 7;
        gB[j] = (const char*)(g_Bcat + (size_t)(n0 + nr) * KCAT + c16 * 8);
        oB[j] = 8192 + sw_off(nr, c16);
    }

    // ---- accumulators: 2 m-tiles x 4 n-tiles x 4 f32
    float c[2][4][4];
    #pragma unroll
    for (int tm = 0; tm < 2; ++tm)
        #pragma unroll
        for (int tn = 0; tn < 4; ++tn)
            #pragma unroll
            for (int q = 0; q < 4; ++q) c[tm][tn][q] = 0.f;

    // ---- ldmatrix per-lane row indices (constant across chunks)
    const int arow[2] = { wm * 32 + 0  + (lane & 15), wm * 32 + 16 + (lane & 15) };
    const int ac16    = lane >> 4;                               // +0 or +1 16B unit
    const int brow[2] = { wn * 32 + 0  + (lane & 7) + ((lane >> 4) << 3),
                          wn * 32 + 16 + (lane & 7) + ((lane >> 4) << 3) };
    const int bc16    = (lane >> 3) & 1;

    // ---- prologue: issue stages 0 and 1
    #pragma unroll
    for (int pre = 0; pre < 2; ++pre) {
        uint32_t s0 = sb + pre * STAGE_BYTES;
        CP_ASYNC16(s0 + oA0, gA0 + pre * 128);
        CP_ASYNC16(s0 + oA1, gA1 + pre * 128);
        #pragma unroll
        for (int j = 0; j < 4; ++j) CP_ASYNC16(s0 + oB[j], gB[j] + pre * 128);
        CP_COMMIT();
    }

    int stage = 0;
    for (int i = 0; i < NCHUNK; ++i) {
        // issue stage i+2
        if (i + 2 < NCHUNK) {
            int st = (i + 2) % NSTAGE;
            uint32_t s0 = sb + st * STAGE_BYTES;
            CP_ASYNC16(s0 + oA0, gA0 + (size_t)(i + 2) * 128);
            CP_ASYNC16(s0 + oA1, gA1 + (size_t)(i + 2) * 128);
            #pragma unroll
            for (int j = 0; j < 4; ++j) CP_ASYNC16(s0 + oB[j], gB[j] + (size_t)(i + 2) * 128);
            CP_COMMIT();
        }
        // wait until stage i's group is complete
        if (i + 2 < NCHUNK)      CP_WAIT(2);
        else if (i + 1 < NCHUNK) CP_WAIT(1);
        else                     CP_WAIT(0);
        __syncthreads();

        const uint32_t sA = sb + stage * STAGE_BYTES;
        const uint32_t sB = sA + 8192;
        #pragma unroll
        for (int ks = 0; ks < 4; ++ks) {          // 4 x k16 per 64-chunk
            const int c16b = ks << 1;
            uint32_t a[2][4], b[2][4];
            #pragma unroll
            for (int tm = 0; tm < 2; ++tm) {
                uint32_t addr = sA + sw_off(arow[tm], c16b + ac16);
                LDMATRIX_X4(a[tm][0], a[tm][1], a[tm][2], a[tm][3], addr);
            }
            #pragma unroll
            for (int np = 0; np < 2; ++np) {      // each covers 2 n8 tiles
                uint32_t addr = sB + sw_off(brow[np], c16b + bc16);
                LDMATRIX_X4(b[np][0], b[np][1], b[np][2], b[np][3], addr);
            }
            #pragma unroll
            for (int tm = 0; tm < 2; ++tm) {
                #pragma unroll
                for (int np = 0; np < 2; ++np) {
                    MMA_BF16(c[tm][2 * np + 0][0], c[tm][2 * np + 0][1], c[tm][2 * np + 0][2], c[tm][2 * np + 0][3],
                             a[tm][0], a[tm][1], a[tm][2], a[tm][3], b[np][0], b[np][1]);
                    MMA_BF16(c[tm][2 * np + 1][0], c[tm][2 * np + 1][1], c[tm][2 * np + 1][2], c[tm][2 * np + 1][3],
                             a[tm][0], a[tm][1], a[tm][2], a[tm][3], b[np][2], b[np][3]);
                }
            }
        }
        __syncthreads();
        stage = (stage + 1 == NSTAGE) ? 0 : stage + 1;
    }

    // ---- epilogue: fragment -> g_Hb  (c0,c1)=(row, 2tg), (c2,c3)=(row+8, 2tg)
    const int g  = lane >> 2;
    const int tg = lane & 3;
    #pragma unroll
    for (int tm = 0; tm < 2; ++tm) {
        int row = m0 + wm * 32 + tm * 16 + g;
        #pragma unroll
        for (int tn = 0; tn < 4; ++tn) {
            int col = n0 + wn * 32 + tn * 8 + 2 * tg;
            float2 v0 = make_float2(c[tm][tn][0], c[tm][tn][1]);
            float2 v1 = make_float2(c[tm][tn][2], c[tm][tn][3]);
            *(float2*)(g_Hb + (size_t)row * (2 * HDIM) + col)       = v0;
            *(float2*)(g_Hb + (size_t)(row + 8) * (2 * HDIM) + col) = v1;
        }
    }
}

// ---------------------------------------------------------------------------
// 4) per-pair epilogue: logit = sum_j relu(H1[i0,j] + H2[i1,j] + b1[j]) * W2[j] + b2
// ---------------------------------------------------------------------------
__global__ __launch_bounds__(256) void pair_kernel(const int* __restrict__ pair_idx,
                                                   const float* __restrict__ b1,
                                                   const float* __restrict__ W2,
                                                   const float* __restrict__ b2,
                                                   float* __restrict__ out) {
    int p = (blockIdx.x << 3) + (threadIdx.x >> 5);
    int lane = threadIdx.x & 31;
    int i0 = pair_idx[2 * p];
    int i1 = pair_idx[2 * p + 1];
    const float4* h0 = (const float4*)(g_Hb + (size_t)i0 * (2 * HDIM));
    const float4* h1 = (const float4*)(g_Hb + (size_t)i1 * (2 * HDIM) + HDIM);
    const float4* B1 = (const float4*)b1;
    const float4* w2 = (const float4*)W2;
    float acc = 0.f;
    #pragma unroll
    for (int j = lane; j < HDIM / 4; j += 32) {
        float4 x0 = h0[j], x1 = h1[j], bb = B1[j], ww = w2[j];
        acc = fmaf(fmaxf(x0.x + x1.x + bb.x, 0.f), ww.x, acc);
        acc = fmaf(fmaxf(x0.y + x1.y + bb.y, 0.f), ww.y, acc);
        acc = fmaf(fmaxf(x0.z + x1.z + bb.z, 0.f), ww.z, acc);
        acc = fmaf(fmaxf(x0.w + x1.w + bb.w, 0.f), ww.w, acc);
    }
    #pragma unroll
    for (int o = 16; o; o >>= 1) acc += __shfl_xor_sync(0xffffffffu, acc, o);
    if (lane == 0) out[p] = acc + b2[0];
}

// ---------------------------------------------------------------------------
extern "C" void kernel_launch(void* const* d_in, const int* in_sizes, int n_in,
                              void* d_out, int out_size) {
    const float* seq  = (const float*)d_in[0];
    const int*   seg  = (const int*)d_in[1];
    const int*   pidx = (const int*)d_in[2];
    const float* W1   = (const float*)d_in[3];
    const float* b1   = (const float*)d_in[4];
    const float* W2   = (const float*)d_in[5];
    const float* b2   = (const float*)d_in[6];
    float* out = (float*)d_out;

    cudaFuncSetAttribute(mma_gemm_kernel, cudaFuncAttributeMaxDynamicSharedMemorySize, SMEM_TOTAL);

    init_kernel<<<2, 256>>>();
    bounds_kernel<<<TOKS / 256, 256>>>(seg);
    convB_kernel<<<dim3(2 * HDIM / 64, HDIM / 64), 256>>>(W1);
    pool_kernel<<<dim3(HDIM / 256, NSEG), 256>>>(seq);
    mma_gemm_kernel<<<dim3(2 * HDIM / 128, NSEG / 64), 256, SMEM_TOTAL>>>();
    pair_kernel<<<NPAIR / 8, 256>>>(pidx, b1, W2, b2, out);
}